// round 2
// baseline (speedup 1.0000x reference)
#include <cuda_runtime.h>
#include <cstdint>

#define NB   8
#define NKB  16
#define SEQL 512
#define HIDD 768
#define NST  4            // s-tiles of 128
#define BM   128
#define BN   128
#define BK   16
#define NKT  (HIDD / BK)  // 48

// Scratch (device globals — no allocation allowed in kernel_launch)
__device__ float g_qn[NB * SEQL * HIDD];
__device__ float g_kn[NKB * SEQL * HIDD];
__device__ float g_partial[NB * NKB * NST];

// ---------------------------------------------------------------------------
// L2 row normalization (768 = 3 * 256 elements per row)
// ---------------------------------------------------------------------------
__device__ __forceinline__ void norm_row(const float* __restrict__ src,
                                         float* __restrict__ dst) {
    float v[3];
    float s = 0.f;
#pragma unroll
    for (int c = 0; c < 3; c++) {
        v[c] = src[threadIdx.x + c * 256];
        s += v[c] * v[c];
    }
#pragma unroll
    for (int o = 16; o; o >>= 1) s += __shfl_xor_sync(0xffffffffu, s, o);
    __shared__ float ws[8];
    __shared__ float s_inv;
    if ((threadIdx.x & 31) == 0) ws[threadIdx.x >> 5] = s;
    __syncthreads();
    if (threadIdx.x == 0) {
        float t = 0.f;
#pragma unroll
        for (int w = 0; w < 8; w++) t += ws[w];
        s_inv = 1.f / fmaxf(sqrtf(t), 1e-12f);
    }
    __syncthreads();
    float iv = s_inv;
#pragma unroll
    for (int c = 0; c < 3; c++) dst[threadIdx.x + c * 256] = v[c] * iv;
}

__global__ __launch_bounds__(256) void norm_q_kernel(const float* __restrict__ in) {
    size_t row = blockIdx.x;
    norm_row(in + row * HIDD, g_qn + row * HIDD);
}
__global__ __launch_bounds__(256) void norm_k_kernel(const float* __restrict__ in) {
    size_t row = blockIdx.x;
    norm_row(in + row * HIDD, g_kn + row * HIDD);
}

// ---------------------------------------------------------------------------
// Fused GEMM + distance-weighted softmax-score kernel.
// One block per (s_tile, j, i). 256 threads = 16x16, each owns an 8x8 C tile.
// acc kept as packed f32x2 pairs along the t (N) direction; inner product
// uses fma.rn.f32x2 (packed fp32, 2x FFMA throughput on sm_103a).
// ---------------------------------------------------------------------------
__global__ __launch_bounds__(256) void li_main_kernel(
    const float* __restrict__ alpha_p,
    const int* __restrict__ q_mask,
    const int* __restrict__ k_mask) {

    const int stile = blockIdx.x;   // 0..3
    const int j     = blockIdx.y;   // 0..15
    const int i     = blockIdx.z;   // 0..7
    const int s0    = stile * BM;

    __shared__ float As[2][BK][BM];
    __shared__ float Bs[2][BK][BN];
    __shared__ float decay[SEQL];
    __shared__ float red[16];

    const int tid = threadIdx.x;

    // distance decay table: exp(-leaky_relu(alpha) * d)
    {
        float ar = *alpha_p;
        float alpha = (ar > 0.f) ? ar : 0.01f * ar;
        for (int d = tid; d < SEQL; d += 256)
            decay[d] = __expf(-alpha * (float)d);
    }

    const float* Abase = g_qn + ((size_t)i * SEQL + s0) * HIDD;
    const float* Bbase = g_kn + (size_t)j * SEQL * HIDD;
    const int*   km    = k_mask + j * SEQL;

    const int ty = tid >> 4;   // 0..15 -> rows ty*8..ty*8+7
    const int tx = tid & 15;   // 0..15 -> cols tx*8..tx*8+7

    // loader mapping: 512 float4 per 128x16 tile; this thread handles rows
    // lr0 and lr0+64 at quad lq0.
    const int lr0 = tid >> 2;
    const int lq0 = tid & 3;

    float rS1[8], rS2[8];
#pragma unroll
    for (int u = 0; u < 8; u++) { rS1[u] = 0.f; rS2[u] = 0.f; }

    __syncthreads();  // decay table ready

    for (int tt = 0; tt < SEQL / BN; tt++) {
        const int t0 = tt * BN;
        const float* Bt = Bbase + (size_t)t0 * HIDD;

        unsigned long long acc[8][4];
#pragma unroll
        for (int u = 0; u < 8; u++)
#pragma unroll
            for (int vp = 0; vp < 4; vp++) acc[u][vp] = 0ULL;

        // prefetch k-tile 0
        float4 a0 = *(const float4*)(Abase + (size_t)lr0 * HIDD + lq0 * 4);
        float4 a1 = *(const float4*)(Abase + (size_t)(lr0 + 64) * HIDD + lq0 * 4);
        float4 b0 = *(const float4*)(Bt + (size_t)lr0 * HIDD + lq0 * 4);
        float4 b1 = *(const float4*)(Bt + (size_t)(lr0 + 64) * HIDD + lq0 * 4);
#pragma unroll
        for (int c = 0; c < 4; c++) {
            As[0][lq0 * 4 + c][lr0]      = ((const float*)&a0)[c];
            As[0][lq0 * 4 + c][lr0 + 64] = ((const float*)&a1)[c];
            Bs[0][lq0 * 4 + c][lr0]      = ((const float*)&b0)[c];
            Bs[0][lq0 * 4 + c][lr0 + 64] = ((const float*)&b1)[c];
        }
        __syncthreads();

        int buf = 0;
        for (int kt = 0; kt < NKT; kt++) {
            if (kt + 1 < NKT) {
                const int k0 = (kt + 1) * BK;
                a0 = *(const float4*)(Abase + (size_t)lr0 * HIDD + k0 + lq0 * 4);
                a1 = *(const float4*)(Abase + (size_t)(lr0 + 64) * HIDD + k0 + lq0 * 4);
                b0 = *(const float4*)(Bt + (size_t)lr0 * HIDD + k0 + lq0 * 4);
                b1 = *(const float4*)(Bt + (size_t)(lr0 + 64) * HIDD + k0 + lq0 * 4);
            }
#pragma unroll
            for (int k = 0; k < BK; k++) {
                float4 af0 = *(const float4*)&As[buf][k][ty * 8];
                float4 af1 = *(const float4*)&As[buf][k][ty * 8 + 4];
                float4 bf0 = *(const float4*)&Bs[buf][k][tx * 8];
                float4 bf1 = *(const float4*)&Bs[buf][k][tx * 8 + 4];

                unsigned long long bp[4];
                asm("mov.b64 %0, {%1, %2};" : "=l"(bp[0]) : "f"(bf0.x), "f"(bf0.y));
                asm("mov.b64 %0, {%1, %2};" : "=l"(bp[1]) : "f"(bf0.z), "f"(bf0.w));
                asm("mov.b64 %0, {%1, %2};" : "=l"(bp[2]) : "f"(bf1.x), "f"(bf1.y));
                asm("mov.b64 %0, {%1, %2};" : "=l"(bp[3]) : "f"(bf1.z), "f"(bf1.w));

                float afs[8] = {af0.x, af0.y, af0.z, af0.w,
                                af1.x, af1.y, af1.z, af1.w};
#pragma unroll
                for (int u = 0; u < 8; u++) {
                    unsigned long long asp;
                    asm("mov.b64 %0, {%1, %1};" : "=l"(asp) : "f"(afs[u]));
#pragma unroll
                    for (int vp = 0; vp < 4; vp++)
                        asm("fma.rn.f32x2 %0, %1, %2, %0;"
                            : "+l"(acc[u][vp]) : "l"(asp), "l"(bp[vp]));
                }
            }
            if (kt + 1 < NKT) {
                const int nb = buf ^ 1;
#pragma unroll
                for (int c = 0; c < 4; c++) {
                    As[nb][lq0 * 4 + c][lr0]      = ((const float*)&a0)[c];
                    As[nb][lq0 * 4 + c][lr0 + 64] = ((const float*)&a1)[c];
                    Bs[nb][lq0 * 4 + c][lr0]      = ((const float*)&b0)[c];
                    Bs[nb][lq0 * 4 + c][lr0 + 64] = ((const float*)&b1)[c];
                }
                __syncthreads();
                buf = nb;
            }
        }

        // epilogue for this t-tile: streaming softmax-weighted score sums
        float cv[8];
#pragma unroll
        for (int v = 0; v < 8; v++)
            cv[v] = (km[t0 + tx * 8 + v] != 0) ? 1.f : 0.f;

#pragma unroll
        for (int u = 0; u < 8; u++) {
            const int srow = s0 + ty * 8 + u;
#pragma unroll
            for (int vp = 0; vp < 4; vp++) {
                float clo, chi;
                asm("mov.b64 {%0, %1}, %2;" : "=f"(clo), "=f"(chi) : "l"(acc[u][vp]));
                const int tcol = t0 + tx * 8 + vp * 2;
                const int dlo = abs(srow - tcol);
                const int dhi = abs(srow - (tcol + 1));
                float elo = cv[vp * 2]     * __expf(clo * decay[dlo]);
                float ehi = cv[vp * 2 + 1] * __expf(chi * decay[dhi]);
                rS1[u] += elo + ehi;
                rS2[u] += elo * clo + ehi * chi;
            }
        }
        // No extra sync needed: next iteration's prefetch writes buffer 0,
        // last read tile lived in buffer 1 (NKT even), and tile-46 data in
        // buffer 0 was fully consumed before the last __syncthreads above.
    }

    // reduce S1/S2 across the 16 lanes sharing each row (tx dimension)
#pragma unroll
    for (int u = 0; u < 8; u++) {
#pragma unroll
        for (int o = 8; o; o >>= 1) {
            rS1[u] += __shfl_xor_sync(0xffffffffu, rS1[u], o);
            rS2[u] += __shfl_xor_sync(0xffffffffu, rS2[u], o);
        }
    }

    if (tx == 0) {
        const int* qm = q_mask + i * SEQL;
        float rowsum = 0.f;
#pragma unroll
        for (int u = 0; u < 8; u++) {
            const int srow = s0 + ty * 8 + u;
            float sc = (rS1[u] > 0.f) ? (rS2[u] / rS1[u]) : 0.f;  // nan_to_num path
            if (qm[srow] == 0) sc = 0.f;                          // q_mask multiply
            rowsum += sc;
        }
        red[ty] = rowsum;
    }
    __syncthreads();
    if (tid == 0) {
        float t = 0.f;
#pragma unroll
        for (int w = 0; w < 16; w++) t += red[w];
        g_partial[(i * NKB + j) * NST + stile] = t;
    }
}

// ---------------------------------------------------------------------------
// Deterministic final reduction over s-tiles -> out[B, KB]
// ---------------------------------------------------------------------------
__global__ void finalize_kernel(float* __restrict__ out) {
    const int p = threadIdx.x;  // 0..127
    float s = 0.f;
#pragma unroll
    for (int t = 0; t < NST; t++) s += g_partial[p * NST + t];
    out[p] = s;
}

// ---------------------------------------------------------------------------
extern "C" void kernel_launch(void* const* d_in, const int* in_sizes, int n_in,
                              void* d_out, int out_size) {
    const float* q     = (const float*)d_in[0];  // [8, 512, 768] f32
    const float* k     = (const float*)d_in[1];  // [16, 512, 768] f32
    const float* alpha = (const float*)d_in[2];  // scalar f32
    const int*   qm    = (const int*)d_in[3];    // [8, 512] i32
    const int*   kmm   = (const int*)d_in[4];    // [16, 512] i32
    float* out = (float*)d_out;                  // [8, 16] f32

    norm_q_kernel<<<NB * SEQL, 256>>>(q);
    norm_k_kernel<<<NKB * SEQL, 256>>>(k);

    dim3 grid(NST, NKB, NB);
    li_main_kernel<<<grid, 256>>>(alpha, qm, kmm);

    finalize_kernel<<<1, 128>>>(out);
}

// round 6
// speedup vs baseline: 3.1746x; 3.1746x over previous
#include <cuda_runtime.h>
#include <cuda_bf16.h>
#include <cstdint>

#define NB   8
#define NKB  16
#define SEQL 512
#define HIDD 768
#define BM   128
#define BN   128
#define BK   32
#define NCH  (HIDD / BK)      // 24
#define NST  (SEQL / BM)      // 4
#define NTT  (SEQL / BN)      // 4
#define ROWB 80               // padded smem row stride in bytes (40 bf16, conflict-free LDSM)
#define ABYTES (BM * ROWB)    // 10240
#define BBYTES (BN * ROWB)    // 10240
#define BUF_BYTES (2 * ABYTES + 2 * BBYTES)   // 40960

#define SM_DTAB 0
#define SM_KMF  2048
#define SM_RS1  2560
#define SM_RS2  3072
#define SM_BUF  3584
#define SMEM_TOTAL (SM_BUF + 2 * BUF_BYTES)   // 85504

// ---- scratch ----
__device__ __nv_bfloat16 g_qh[NB * SEQL * HIDD];
__device__ __nv_bfloat16 g_ql[NB * SEQL * HIDD];
__device__ __nv_bfloat16 g_kh[NKB * SEQL * HIDD];
__device__ __nv_bfloat16 g_kl[NKB * SEQL * HIDD];
__device__ float g_pS1[NB * NKB * NST * NTT * BM];
__device__ float g_pS2[NB * NKB * NST * NTT * BM];

// ---------------------------------------------------------------------------
__device__ __forceinline__ uint32_t smem_to_u32(const void* p) {
    uint32_t a;
    asm("{ .reg .u64 t; cvta.to.shared.u64 t, %1; cvt.u32.u64 %0, t; }" : "=r"(a) : "l"(p));
    return a;
}
#define CP16(sa, ga) \
    asm volatile("cp.async.cg.shared.global [%0], [%1], 16;" :: "r"(sa), "l"(ga))
#define CP_COMMIT() asm volatile("cp.async.commit_group;" ::: "memory")
#define CP_WAIT(n)  asm volatile("cp.async.wait_group %0;" :: "n"(n) : "memory")
#define LDSM4(r, addr) \
    asm volatile("ldmatrix.sync.aligned.m8n8.x4.shared.b16 {%0,%1,%2,%3}, [%4];" \
        : "=r"((r)[0]), "=r"((r)[1]), "=r"((r)[2]), "=r"((r)[3]) : "r"(addr))

__device__ __forceinline__ void mma_bf16(float* c, const uint32_t* a, const uint32_t* b) {
    asm volatile(
        "mma.sync.aligned.m16n8k16.row.col.f32.bf16.bf16.f32 "
        "{%0,%1,%2,%3}, {%4,%5,%6,%7}, {%8,%9}, {%0,%1,%2,%3};"
        : "+f"(c[0]), "+f"(c[1]), "+f"(c[2]), "+f"(c[3])
        : "r"(a[0]), "r"(a[1]), "r"(a[2]), "r"(a[3]), "r"(b[0]), "r"(b[1]));
}

// ---------------------------------------------------------------------------
// L2 normalize + bf16 hi/lo split
// ---------------------------------------------------------------------------
__device__ __forceinline__ void norm_split(const float* __restrict__ src,
                                           __nv_bfloat16* __restrict__ hid,
                                           __nv_bfloat16* __restrict__ lod) {
    float v[3];
    float s = 0.f;
#pragma unroll
    for (int c = 0; c < 3; c++) {
        v[c] = src[threadIdx.x + c * 256];
        s += v[c] * v[c];
    }
#pragma unroll
    for (int o = 16; o; o >>= 1) s += __shfl_xor_sync(0xffffffffu, s, o);
    __shared__ float ws[8];
    __shared__ float s_inv;
    if ((threadIdx.x & 31) == 0) ws[threadIdx.x >> 5] = s;
    __syncthreads();
    if (threadIdx.x == 0) {
        float t = 0.f;
#pragma unroll
        for (int w = 0; w < 8; w++) t += ws[w];
        s_inv = 1.f / fmaxf(sqrtf(t), 1e-12f);
    }
    __syncthreads();
    float iv = s_inv;
#pragma unroll
    for (int c = 0; c < 3; c++) {
        float x = v[c] * iv;
        __nv_bfloat16 h = __float2bfloat16(x);
        float lo = x - __bfloat162float(h);
        hid[threadIdx.x + c * 256] = h;
        lod[threadIdx.x + c * 256] = __float2bfloat16(lo);
    }
}
__global__ __launch_bounds__(256) void norm_q_kernel(const float* __restrict__ in) {
    size_t row = blockIdx.x;
    norm_split(in + row * HIDD, g_qh + row * HIDD, g_ql + row * HIDD);
}
__global__ __launch_bounds__(256) void norm_k_kernel(const float* __restrict__ in) {
    size_t row = blockIdx.x;
    norm_split(in + row * HIDD, g_kh + row * HIDD, g_kl + row * HIDD);
}

// ---------------------------------------------------------------------------
// Main: bf16x3 mma.sync GEMM (128x128xK768) + fused streaming softmax-score
// ---------------------------------------------------------------------------
__global__ __launch_bounds__(256, 2) void li_mma_kernel(
    const float* __restrict__ alpha_p,
    const int* __restrict__ k_mask) {

    extern __shared__ char smem[];
    const uint32_t sb = smem_to_u32(smem);
    const int tid = threadIdx.x;
    const int lane = tid & 31;
    const int w = tid >> 5;
    const int warp_m = w & 3;     // 4 warps in M: 32 rows each
    const int warp_n = w >> 2;    // 2 warps in N: 64 cols each
    const int stile = blockIdx.x, ttile = blockIdx.y, ij = blockIdx.z;
    const int i = ij >> 4, j = ij & 15;
    const int s0 = stile * BM, t0 = ttile * BN;

    float* dtab = (float*)(smem + SM_DTAB);
    float* kmf  = (float*)(smem + SM_KMF);
    float* rs1s = (float*)(smem + SM_RS1);
    float* rs2s = (float*)(smem + SM_RS2);

    {
        float ar = *alpha_p;
        float alpha = (ar > 0.f) ? ar : 0.01f * ar;
        for (int d = tid; d < SEQL; d += 256) dtab[d] = __expf(-alpha * (float)d);
        for (int t = tid; t < BN; t += 256)
            kmf[t] = (k_mask[j * SEQL + t0 + t] != 0) ? 1.f : 0.f;
        if (tid < BM) { rs1s[tid] = 0.f; rs2s[tid] = 0.f; }
    }
    __syncthreads();

    const __nv_bfloat16* Ah = g_qh + ((size_t)i * SEQL + s0) * HIDD;
    const __nv_bfloat16* Al = g_ql + ((size_t)i * SEQL + s0) * HIDD;
    const __nv_bfloat16* Bh = g_kh + ((size_t)j * SEQL + t0) * HIDD;
    const __nv_bfloat16* Bl = g_kl + ((size_t)j * SEQL + t0) * HIDD;

    float acc[2][8][4];
#pragma unroll
    for (int mi = 0; mi < 2; mi++)
#pragma unroll
        for (int ni = 0; ni < 8; ni++)
#pragma unroll
            for (int e = 0; e < 4; e++) acc[mi][ni][e] = 0.f;

    auto load_chunk = [&](int ch, int b) {
        const uint32_t base = sb + SM_BUF + b * BUF_BYTES;
        const int k0 = ch * BK;
#pragma unroll
        for (int half = 0; half < 2; half++) {
            const int idx = tid + half * 256;          // 0..511
            const int row = idx >> 2, q = idx & 3;     // 128 rows x 4 quads
            const size_t go = (size_t)row * HIDD + k0 + q * 8;
            const uint32_t so = base + row * ROWB + q * 16;
            CP16(so, Ah + go);
            CP16(so + ABYTES, Al + go);
            const uint32_t so2 = base + 2 * ABYTES + row * ROWB + q * 16;
            CP16(so2, Bh + go);
            CP16(so2 + BBYTES, Bl + go);
        }
    };

    auto mma_chunk = [&](int b) {
        const uint32_t abase = sb + SM_BUF + b * BUF_BYTES;
        const uint32_t bbase = abase + 2 * ABYTES;
#pragma unroll
        for (int ks = 0; ks < 2; ks++) {
            const int kb = ks * 32;   // 16 elems * 2B
            uint32_t ah[2][4], al[2][4];
#pragma unroll
            for (int mi = 0; mi < 2; mi++) {
                const uint32_t r = warp_m * 32 + mi * 16 + (lane & 15);
                const uint32_t ad = abase + r * ROWB + kb + (lane >> 4) * 16;
                LDSM4(ah[mi], ad);
                LDSM4(al[mi], ad + ABYTES);
            }
#pragma unroll
            for (int nh = 0; nh < 2; nh++) {
                uint32_t bhr[2][4], blr[2][4];
#pragma unroll
                for (int bi = 0; bi < 2; bi++) {
                    const int n0 = warp_n * 64 + nh * 32 + bi * 16;
                    const uint32_t rr = n0 + ((lane >> 4) * 8) + (lane & 7);
                    const uint32_t bd = bbase + rr * ROWB + kb + (((lane >> 3) & 1) * 16);
                    LDSM4(bhr[bi], bd);
                    LDSM4(blr[bi], bd + BBYTES);
                }
#pragma unroll
                for (int mi = 0; mi < 2; mi++)
#pragma unroll
                    for (int f = 0; f < 4; f++) {
                        const uint32_t* bhp = &bhr[f >> 1][(f & 1) * 2];
                        const uint32_t* blp = &blr[f >> 1][(f & 1) * 2];
                        float* c = acc[mi][nh * 4 + f];
                        mma_bf16(c, ah[mi], bhp);   // hi*hi
                        mma_bf16(c, ah[mi], blp);   // hi*lo
                        mma_bf16(c, al[mi], bhp);   // lo*hi
                    }
            }
        }
    };

    load_chunk(0, 0);
    CP_COMMIT();
    for (int ch = 0; ch < NCH; ch++) {
        if (ch + 1 < NCH) {
            load_chunk(ch + 1, (ch + 1) & 1);
            CP_COMMIT();
            CP_WAIT(1);
        } else {
            CP_WAIT(0);
        }
        __syncthreads();
        mma_chunk(ch & 1);
        __syncthreads();
    }

    // ---- fused epilogue: streaming softmax-score partials ----
    float prs1[2][2], prs2[2][2];
#pragma unroll
    for (int mi = 0; mi < 2; mi++)
#pragma unroll
        for (int h = 0; h < 2; h++) { prs1[mi][h] = 0.f; prs2[mi][h] = 0.f; }

#pragma unroll
    for (int mi = 0; mi < 2; mi++) {
        const int rlo = s0 + warp_m * 32 + mi * 16 + (lane >> 2);
#pragma unroll
        for (int ni = 0; ni < 8; ni++) {
            const int tloc = warp_n * 64 + ni * 8 + (lane & 3) * 2;
#pragma unroll
            for (int e = 0; e < 4; e++) {
                const int row = rlo + (e >> 1) * 8;
                const int tc = t0 + tloc + (e & 1);
                const float cv = acc[mi][ni][e];
                int d = row - tc; if (d < 0) d = -d;
                const float ee = kmf[tloc + (e & 1)] * __expf(cv * dtab[d]);
                prs1[mi][e >> 1] += ee;
                prs2[mi][e >> 1] += ee * cv;
            }
        }
    }

#pragma unroll
    for (int mi = 0; mi < 2; mi++)
#pragma unroll
        for (int h = 0; h < 2; h++) {
            float v1 = prs1[mi][h], v2 = prs2[mi][h];
            v1 += __shfl_xor_sync(0xffffffffu, v1, 1);
            v1 += __shfl_xor_sync(0xffffffffu, v1, 2);
            v2 += __shfl_xor_sync(0xffffffffu, v2, 1);
            v2 += __shfl_xor_sync(0xffffffffu, v2, 2);
            if ((lane & 3) == 0) {
                const int lr = warp_m * 32 + mi * 16 + (lane >> 2) + h * 8;
                atomicAdd(&rs1s[lr], v1);   // exactly 2 addends/row (warp_n 0,1)
                atomicAdd(&rs2s[lr], v2);   // -> order-independent, deterministic
            }
        }
    __syncthreads();

    if (tid < BM) {
        const size_t pidx = (((size_t)ij * NST + stile) * NTT + ttile) * BM + tid;
        g_pS1[pidx] = rs1s[tid];
        g_pS2[pidx] = rs2s[tid];
    }
}

// ---------------------------------------------------------------------------
// Finalize: combine t-tiles, softmax ratio, q-mask, row-sum -> out[B,KB]
// ---------------------------------------------------------------------------
__global__ __launch_bounds__(256) void finalize_kernel(const int* __restrict__ q_mask,
                                                       float* __restrict__ out) {
    const int z = blockIdx.x;           // ij = i*16+j
    const int i = z >> 4;
    __shared__ float red[256];
    float acc = 0.f;
    for (int s = threadIdx.x; s < SEQL; s += 256) {
        const int stile = s >> 7, r = s & 127;
        const size_t base = (((size_t)z * NST + stile) * NTT) * BM + r;
        float S1 = 0.f, S2 = 0.f;
#pragma unroll
        for (int tt = 0; tt < NTT; tt++) {   // fixed order: deterministic
            S1 += g_pS1[base + (size_t)tt * BM];
            S2 += g_pS2[base + (size_t)tt * BM];
        }
        float sc = (S1 > 0.f) ? (S2 / S1) : 0.f;
        if (q_mask[i * SEQL + s] == 0) sc = 0.f;
        acc += sc;
    }
    red[threadIdx.x] = acc;
    __syncthreads();
    for (int o = 128; o; o >>= 1) {
        if (threadIdx.x < (unsigned)o) red[threadIdx.x] += red[threadIdx.x + o];
        __syncthreads();
    }
    if (threadIdx.x == 0) out[z] = red[0];
}

// ---------------------------------------------------------------------------
extern "C" void kernel_launch(void* const* d_in, const int* in_sizes, int n_in,
                              void* d_out, int out_size) {
    const float* q     = (const float*)d_in[0];
    const float* k     = (const float*)d_in[1];
    const float* alpha = (const float*)d_in[2];
    const int*   qm    = (const int*)d_in[3];
    const int*   kmm   = (const int*)d_in[4];
    float* out = (float*)d_out;

    cudaFuncSetAttribute(li_mma_kernel, cudaFuncAttributeMaxDynamicSharedMemorySize,
                         SMEM_TOTAL);

    norm_q_kernel<<<NB * SEQL, 256>>>(q);
    norm_k_kernel<<<NKB * SEQL, 256>>>(k);

    dim3 grid(NST, NTT, NB * NKB);
    li_mma_kernel<<<grid, 256, SMEM_TOTAL>>>(alpha, kmm);

    finalize_kernel<<<NB * NKB, 256>>>(qm, out);
}

// round 11
// speedup vs baseline: 4.9124x; 1.5474x over previous
#include <cuda_runtime.h>
#include <cuda_bf16.h>
#include <cstdint>

#define NB   8
#define NKB  16
#define SEQL 512
#define HIDD 768
#define BM   128
#define BN   128
#define BK   32
#define NCH  (HIDD / BK)      // 24
#define NST  (SEQL / BM)      // 4
#define NTT  (SEQL / BN)      // 4
#define ROWB 80               // padded smem row stride (conflict-free LDSM)
#define ABYTES (BM * ROWB)
#define BBYTES (BN * ROWB)
#define BUF_BYTES (2 * ABYTES + 2 * BBYTES)   // 40960

#define SM_DTAB 0
#define SM_KMF  2048
#define SM_TIDX 2560
#define SM_SIDX 3072
#define SM_RS1  3584
#define SM_RS2  4096
#define SM_BUF  4608
#define SMEM_TOTAL (SM_BUF + 2 * BUF_BYTES)   // 86528

// ---- scratch (compacted layouts) ----
__device__ __nv_bfloat16 g_qh[NB * SEQL * HIDD];
__device__ __nv_bfloat16 g_ql[NB * SEQL * HIDD];
__device__ __nv_bfloat16 g_kh[NKB * SEQL * HIDD];
__device__ __nv_bfloat16 g_kl[NKB * SEQL * HIDD];
__device__ float g_pS1[NB * NKB * NST * NTT * BM];
__device__ float g_pS2[NB * NKB * NST * NTT * BM];
__device__ int g_spos[NB * SEQL], g_tpos[NKB * SEQL];
__device__ int g_sidx[NB * SEQL], g_tidx[NKB * SEQL];
__device__ int g_scnt[NB], g_kcnt[NKB];

// ---------------------------------------------------------------------------
__device__ __forceinline__ uint32_t smem_to_u32(const void* p) {
    uint32_t a;
    asm("{ .reg .u64 t; cvta.to.shared.u64 t, %1; cvt.u32.u64 %0, t; }" : "=r"(a) : "l"(p));
    return a;
}
#define CP16(sa, ga) \
    asm volatile("cp.async.cg.shared.global [%0], [%1], 16;" :: "r"(sa), "l"(ga))
#define CP_COMMIT() asm volatile("cp.async.commit_group;" ::: "memory")
#define CP_WAIT(n)  asm volatile("cp.async.wait_group %0;" :: "n"(n) : "memory")
#define LDSM4(r, addr) \
    asm volatile("ldmatrix.sync.aligned.m8n8.x4.shared.b16 {%0,%1,%2,%3}, [%4];" \
        : "=r"((r)[0]), "=r"((r)[1]), "=r"((r)[2]), "=r"((r)[3]) : "r"(addr))

__device__ __forceinline__ void mma_bf16(float* c, const uint32_t* a, const uint32_t* b) {
    asm volatile(
        "mma.sync.aligned.m16n8k16.row.col.f32.bf16.bf16.f32 "
        "{%0,%1,%2,%3}, {%4,%5,%6,%7}, {%8,%9}, {%0,%1,%2,%3};"
        : "+f"(c[0]), "+f"(c[1]), "+f"(c[2]), "+f"(c[3])
        : "r"(a[0]), "r"(a[1]), "r"(a[2]), "r"(a[3]), "r"(b[0]), "r"(b[1]));
}

// ---------------------------------------------------------------------------
// Mask prefix-scan: compact<->orig maps + counts. One block per batch row.
// ---------------------------------------------------------------------------
__global__ __launch_bounds__(512) void scan_kernel(const int* __restrict__ qm,
                                                   const int* __restrict__ km) {
    const int b = blockIdx.x;
    const bool isq = (b < NB);
    const int* m = isq ? (qm + b * SEQL) : (km + (b - NB) * SEQL);
    int* pos = isq ? (g_spos + b * SEQL) : (g_tpos + (b - NB) * SEQL);
    int* idx = isq ? (g_sidx + b * SEQL) : (g_tidx + (b - NB) * SEQL);
    __shared__ int sc[SEQL];
    const int tid = threadIdx.x;
    const int v = (m[tid] != 0);
    sc[tid] = v;
    __syncthreads();
    for (int o = 1; o < SEQL; o <<= 1) {
        int t = (tid >= o) ? sc[tid - o] : 0;
        __syncthreads();
        sc[tid] += t;
        __syncthreads();
    }
    const int incl = sc[tid];
    const int total = sc[SEQL - 1];
    if (v) { pos[tid] = incl - 1; idx[incl - 1] = tid; }
    else pos[tid] = -1;
    if (tid >= total) idx[tid] = 0;   // disjoint from scatter range
    if (tid == 0) { if (isq) g_scnt[b] = total; else g_kcnt[b - NB] = total; }
}

// ---------------------------------------------------------------------------
// L2 normalize + bf16 hi/lo split, scattered to compacted position
// ---------------------------------------------------------------------------
__device__ __forceinline__ void norm_split(const float* __restrict__ src,
                                           __nv_bfloat16* __restrict__ hid,
                                           __nv_bfloat16* __restrict__ lod) {
    float v[3];
    float s = 0.f;
#pragma unroll
    for (int c = 0; c < 3; c++) {
        v[c] = src[threadIdx.x + c * 256];
        s += v[c] * v[c];
    }
#pragma unroll
    for (int o = 16; o; o >>= 1) s += __shfl_xor_sync(0xffffffffu, s, o);
    __shared__ float ws[8];
    __shared__ float s_inv;
    if ((threadIdx.x & 31) == 0) ws[threadIdx.x >> 5] = s;
    __syncthreads();
    if (threadIdx.x == 0) {
        float t = 0.f;
#pragma unroll
        for (int w = 0; w < 8; w++) t += ws[w];
        s_inv = 1.f / fmaxf(sqrtf(t), 1e-12f);
    }
    __syncthreads();
    float iv = s_inv;
#pragma unroll
    for (int c = 0; c < 3; c++) {
        float x = v[c] * iv;
        __nv_bfloat16 h = __float2bfloat16(x);
        float lo = x - __bfloat162float(h);
        hid[threadIdx.x + c * 256] = h;
        lod[threadIdx.x + c * 256] = __float2bfloat16(lo);
    }
}
__global__ __launch_bounds__(256) void norm_q_kernel(const float* __restrict__ in,
                                                     const int* __restrict__ qm) {
    const int row = blockIdx.x;             // i*512+s
    if (qm[row] == 0) return;               // block-uniform
    const int i = row >> 9;
    const size_t dst = (size_t)i * SEQL + g_spos[row];
    norm_split(in + (size_t)row * HIDD, g_qh + dst * HIDD, g_ql + dst * HIDD);
}
__global__ __launch_bounds__(256) void norm_k_kernel(const float* __restrict__ in,
                                                     const int* __restrict__ km) {
    const int row = blockIdx.x;
    if (km[row] == 0) return;
    const int j = row >> 9;
    const size_t dst = (size_t)j * SEQL + g_tpos[row];
    norm_split(in + (size_t)row * HIDD, g_kh + dst * HIDD, g_kl + dst * HIDD);
}

// ---------------------------------------------------------------------------
// Zero-fill padding rows up to the next 128-tile boundary
// ---------------------------------------------------------------------------
__global__ __launch_bounds__(256) void pad_zero_kernel() {
    const int b = blockIdx.x;
    const bool isq = (b < NB);
    const int cnt = isq ? g_scnt[b] : g_kcnt[b - NB];
    int pad = (cnt + 127) & ~127;
    if (pad > SEQL) pad = SEQL;
    __nv_bfloat16* h = isq ? (g_qh + (size_t)b * SEQL * HIDD)
                           : (g_kh + (size_t)(b - NB) * SEQL * HIDD);
    __nv_bfloat16* l = isq ? (g_ql + (size_t)b * SEQL * HIDD)
                           : (g_kl + (size_t)(b - NB) * SEQL * HIDD);
    const int n = (pad - cnt) * HIDD;
    const __nv_bfloat16 z = __float2bfloat16(0.f);
    for (int e = threadIdx.x; e < n; e += 256) {
        h[(size_t)cnt * HIDD + e] = z;
        l[(size_t)cnt * HIDD + e] = z;
    }
}

// ---------------------------------------------------------------------------
// Main: bf16x3 mma.sync GEMM on compacted tiles + fused softmax-score
// ---------------------------------------------------------------------------
__global__ __launch_bounds__(256, 2) void li_mma_kernel(
    const float* __restrict__ alpha_p) {

    extern __shared__ char smem[];
    const uint32_t sb = smem_to_u32(smem);
    const int tid = threadIdx.x;
    const int lane = tid & 31;
    const int w = tid >> 5;
    const int warp_m = w & 3;
    const int warp_n = w >> 2;
    const int stile = blockIdx.x, ttile = blockIdx.y, ij = blockIdx.z;
    const int i = ij >> 4, j = ij & 15;
    const int s0 = stile * BM, t0 = ttile * BN;

    const int scnt = g_scnt[i], kcnt = g_kcnt[j];
    const int qtiles = (scnt + BM - 1) >> 7;
    const int ktiles = (kcnt + BN - 1) >> 7;
    const size_t pidx0 = (((size_t)ij * NST + stile) * NTT + ttile) * BM;

    if (stile >= qtiles || ttile >= ktiles) {
        if (tid < BM) { g_pS1[pidx0 + tid] = 0.f; g_pS2[pidx0 + tid] = 0.f; }
        return;
    }

    float* dtab = (float*)(smem + SM_DTAB);
    float* kmf  = (float*)(smem + SM_KMF);
    int*   tdx  = (int*)(smem + SM_TIDX);
    int*   sdx  = (int*)(smem + SM_SIDX);
    float* rs1s = (float*)(smem + SM_RS1);
    float* rs2s = (float*)(smem + SM_RS2);

    {
        float ar = *alpha_p;
        float alpha = (ar > 0.f) ? ar : 0.01f * ar;
        for (int d = tid; d < SEQL; d += 256) dtab[d] = __expf(-alpha * (float)d);
        if (tid < BN) {
            kmf[tid] = (t0 + tid < kcnt) ? 1.f : 0.f;
            tdx[tid] = g_tidx[j * SEQL + t0 + tid];
        }
        if (tid >= BN && tid < BN + BM) {
            const int r = tid - BN;
            sdx[r] = g_sidx[i * SEQL + s0 + r];
            rs1s[r] = 0.f; rs2s[r] = 0.f;
        }
    }
    __syncthreads();

    const __nv_bfloat16* Ah = g_qh + ((size_t)i * SEQL + s0) * HIDD;
    const __nv_bfloat16* Al = g_ql + ((size_t)i * SEQL + s0) * HIDD;
    const __nv_bfloat16* Bh = g_kh + ((size_t)j * SEQL + t0) * HIDD;
    const __nv_bfloat16* Bl = g_kl + ((size_t)j * SEQL + t0) * HIDD;

    float acc[2][8][4];
#pragma unroll
    for (int mi = 0; mi < 2; mi++)
#pragma unroll
        for (int ni = 0; ni < 8; ni++)
#pragma unroll
            for (int e = 0; e < 4; e++) acc[mi][ni][e] = 0.f;

    auto load_chunk = [&](int ch, int b) {
        const uint32_t base = sb + SM_BUF + b * BUF_BYTES;
        const int k0 = ch * BK;
#pragma unroll
        for (int half = 0; half < 2; half++) {
            const int idx = tid + half * 256;
            const int row = idx >> 2, q = idx & 3;
            const size_t go = (size_t)row * HIDD + k0 + q * 8;
            const uint32_t so = base + row * ROWB + q * 16;
            CP16(so, Ah + go);
            CP16(so + ABYTES, Al + go);
            const uint32_t so2 = base + 2 * ABYTES + row * ROWB + q * 16;
            CP16(so2, Bh + go);
            CP16(so2 + BBYTES, Bl + go);
        }
    };

    auto mma_chunk = [&](int b) {
        const uint32_t abase = sb + SM_BUF + b * BUF_BYTES;
        const uint32_t bbase = abase + 2 * ABYTES;
#pragma unroll
        for (int ks = 0; ks < 2; ks++) {
            const int kb = ks * 32;
            uint32_t ah[2][4], al[2][4];
#pragma unroll
            for (int mi = 0; mi < 2; mi++) {
                const uint32_t r = warp_m * 32 + mi * 16 + (lane & 15);
                const uint32_t ad = abase + r * ROWB + kb + (lane >> 4) * 16;
                LDSM4(ah[mi], ad);
                LDSM4(al[mi], ad + ABYTES);
            }
#pragma unroll
            for (int nh = 0; nh < 2; nh++) {
                uint32_t bhr[2][4], blr[2][4];
#pragma unroll
                for (int bi = 0; bi < 2; bi++) {
                    const int n0 = warp_n * 64 + nh * 32 + bi * 16;
                    const uint32_t rr = n0 + ((lane >> 4) * 8) + (lane & 7);
                    const uint32_t bd = bbase + rr * ROWB + kb + (((lane >> 3) & 1) * 16);
                    LDSM4(bhr[bi], bd);
                    LDSM4(blr[bi], bd + BBYTES);
                }
#pragma unroll
                for (int mi = 0; mi < 2; mi++)
#pragma unroll
                    for (int f = 0; f < 4; f++) {
                        const uint32_t* bhp = &bhr[f >> 1][(f & 1) * 2];
                        const uint32_t* blp = &blr[f >> 1][(f & 1) * 2];
                        float* c = acc[mi][nh * 4 + f];
                        mma_bf16(c, ah[mi], bhp);   // hi*hi
                        mma_bf16(c, ah[mi], blp);   // hi*lo
                        mma_bf16(c, al[mi], bhp);   // lo*hi
                    }
            }
        }
    };

    load_chunk(0, 0);
    CP_COMMIT();
    for (int ch = 0; ch < NCH; ch++) {
        if (ch + 1 < NCH) {
            load_chunk(ch + 1, (ch + 1) & 1);
            CP_COMMIT();
            CP_WAIT(1);
        } else {
            CP_WAIT(0);
        }
        __syncthreads();
        mma_chunk(ch & 1);
        __syncthreads();
    }

    // ---- fused epilogue with original-index distance decay ----
    float prs1[2][2], prs2[2][2];
#pragma unroll
    for (int mi = 0; mi < 2; mi++)
#pragma unroll
        for (int h = 0; h < 2; h++) { prs1[mi][h] = 0.f; prs2[mi][h] = 0.f; }

#pragma unroll
    for (int mi = 0; mi < 2; mi++) {
        const int rloc = warp_m * 32 + mi * 16 + (lane >> 2);
        const int sor[2] = { sdx[rloc], sdx[rloc + 8] };
#pragma unroll
        for (int ni = 0; ni < 8; ni++) {
            const int tloc = warp_n * 64 + ni * 8 + (lane & 3) * 2;
#pragma unroll
            for (int e = 0; e < 4; e++) {
                const int sorr = sor[e >> 1];
                const int torr = tdx[tloc + (e & 1)];
                const float cv = acc[mi][ni][e];
                int d = sorr - torr; if (d < 0) d = -d;
                const float ee = kmf[tloc + (e & 1)] * __expf(cv * dtab[d]);
                prs1[mi][e >> 1] += ee;
                prs2[mi][e >> 1] += ee * cv;
            }
        }
    }

#pragma unroll
    for (int mi = 0; mi < 2; mi++)
#pragma unroll
        for (int h = 0; h < 2; h++) {
            float v1 = prs1[mi][h], v2 = prs2[mi][h];
            v1 += __shfl_xor_sync(0xffffffffu, v1, 1);
            v1 += __shfl_xor_sync(0xffffffffu, v1, 2);
            v2 += __shfl_xor_sync(0xffffffffu, v2, 1);
            v2 += __shfl_xor_sync(0xffffffffu, v2, 2);
            if ((lane & 3) == 0) {
                const int lr = warp_m * 32 + mi * 16 + (lane >> 2) + h * 8;
                atomicAdd(&rs1s[lr], v1);   // exactly 2 addends/row -> deterministic
                atomicAdd(&rs2s[lr], v2);
            }
        }
    __syncthreads();

    if (tid < BM) {
        g_pS1[pidx0 + tid] = rs1s[tid];
        g_pS2[pidx0 + tid] = rs2s[tid];
    }
}

// ---------------------------------------------------------------------------
// Finalize: sum compact rows (pads self-cancel: S2=0 or S1=0)
// ---------------------------------------------------------------------------
__global__ __launch_bounds__(256) void finalize_kernel(float* __restrict__ out) {
    const int z = blockIdx.x;           // ij = i*16+j
    __shared__ float red[256];
    float acc = 0.f;
    for (int s = threadIdx.x; s < SEQL; s += 256) {
        const int stile = s >> 7, r = s & 127;
        const size_t base = (((size_t)z * NST + stile) * NTT) * BM + r;
        float S1 = 0.f, S2 = 0.f;
#pragma unroll
        for (int tt = 0; tt < NTT; tt++) {
            S1 += g_pS1[base + (size_t)tt * BM];
            S2 += g_pS2[base + (size_t)tt * BM];
        }
        acc += (S1 > 0.f) ? (S2 / S1) : 0.f;
    }
    red[threadIdx.x] = acc;
    __syncthreads();
    for (int o = 128; o; o >>= 1) {
        if (threadIdx.x < (unsigned)o) red[threadIdx.x] += red[threadIdx.x + o];
        __syncthreads();
    }
    if (threadIdx.x == 0) out[z] = red[0];
}

// ---------------------------------------------------------------------------
extern "C" void kernel_launch(void* const* d_in, const int* in_sizes, int n_in,
                              void* d_out, int out_size) {
    const float* q     = (const float*)d_in[0];
    const float* k     = (const float*)d_in[1];
    const float* alpha = (const float*)d_in[2];
    const int*   qm    = (const int*)d_in[3];
    const int*   kmm   = (const int*)d_in[4];
    float* out = (float*)d_out;

    cudaFuncSetAttribute(li_mma_kernel, cudaFuncAttributeMaxDynamicSharedMemorySize,
                         SMEM_TOTAL);

    scan_kernel<<<NB + NKB, 512>>>(qm, kmm);
    norm_q_kernel<<<NB * SEQL, 256>>>(q, qm);
    norm_k_kernel<<<NKB * SEQL, 256>>>(k, kmm);
    pad_zero_kernel<<<NB + NKB, 256>>>();

    dim3 grid(NST, NTT, NB * NKB);
    li_mma_kernel<<<grid, 256, SMEM_TOTAL>>>(alpha);

    finalize_kernel<<<NB * NKB, 256>>>(out);
}

// round 15
// speedup vs baseline: 7.7121x; 1.5699x over previous
#include <cuda_runtime.h>
#include <cuda_bf16.h>
#include <cstdint>

#define NB   8
#define NKB  16
#define SEQL 512
#define HIDD 768
#define BM   128
#define BN   128
#define BK   32
#define NCH  (HIDD / BK)      // 24
#define NST  (SEQL / BM)      // 4
#define NTT  (SEQL / BN)      // 4
#define ROWB 80               // padded smem row stride (conflict-free LDSM)
#define ABYTES (BM * ROWB)
#define BBYTES (BN * ROWB)
#define BUF_BYTES (2 * ABYTES + 2 * BBYTES)   // 40960

#define SM_DTAB 0
#define SM_KMF  2048
#define SM_TIDX 2560
#define SM_SIDX 3072
#define SM_RS1  3584
#define SM_RS2  4096
#define SM_BUF  4608
#define SMEM_TOTAL (SM_BUF + 2 * BUF_BYTES)   // 86528

// ---- scratch (compacted layouts) ----
__device__ __nv_bfloat16 g_qh[NB * SEQL * HIDD];
__device__ __nv_bfloat16 g_ql[NB * SEQL * HIDD];
__device__ __nv_bfloat16 g_kh[NKB * SEQL * HIDD];
__device__ __nv_bfloat16 g_kl[NKB * SEQL * HIDD];
__device__ float g_pS1[NB * NKB * NST * NTT * BM];
__device__ float g_pS2[NB * NKB * NST * NTT * BM];
__device__ int g_spos[NB * SEQL], g_tpos[NKB * SEQL];
__device__ int g_sidx[NB * SEQL], g_tidx[NKB * SEQL];
__device__ int g_scnt[NB], g_kcnt[NKB];

// ---------------------------------------------------------------------------
__device__ __forceinline__ uint32_t smem_to_u32(const void* p) {
    uint32_t a;
    asm("{ .reg .u64 t; cvta.to.shared.u64 t, %1; cvt.u32.u64 %0, t; }" : "=r"(a) : "l"(p));
    return a;
}
#define CP16(sa, ga) \
    asm volatile("cp.async.cg.shared.global [%0], [%1], 16;" :: "r"(sa), "l"(ga))
#define CP_COMMIT() asm volatile("cp.async.commit_group;" ::: "memory")
#define CP_WAIT(n)  asm volatile("cp.async.wait_group %0;" :: "n"(n) : "memory")
#define LDSM4(r, addr) \
    asm volatile("ldmatrix.sync.aligned.m8n8.x4.shared.b16 {%0,%1,%2,%3}, [%4];" \
        : "=r"((r)[0]), "=r"((r)[1]), "=r"((r)[2]), "=r"((r)[3]) : "r"(addr))

__device__ __forceinline__ void mma_bf16(float* c, const uint32_t* a, const uint32_t* b) {
    asm volatile(
        "mma.sync.aligned.m16n8k16.row.col.f32.bf16.bf16.f32 "
        "{%0,%1,%2,%3}, {%4,%5,%6,%7}, {%8,%9}, {%0,%1,%2,%3};"
        : "+f"(c[0]), "+f"(c[1]), "+f"(c[2]), "+f"(c[3])
        : "r"(a[0]), "r"(a[1]), "r"(a[2]), "r"(a[3]), "r"(b[0]), "r"(b[1]));
}

// ---------------------------------------------------------------------------
// Mask prefix-scan: compact<->orig maps + counts. One block per batch row.
// ---------------------------------------------------------------------------
__global__ __launch_bounds__(512) void scan_kernel(const int* __restrict__ qm,
                                                   const int* __restrict__ km) {
    const int b = blockIdx.x;
    const bool isq = (b < NB);
    const int* m = isq ? (qm + b * SEQL) : (km + (b - NB) * SEQL);
    int* pos = isq ? (g_spos + b * SEQL) : (g_tpos + (b - NB) * SEQL);
    int* idx = isq ? (g_sidx + b * SEQL) : (g_tidx + (b - NB) * SEQL);
    __shared__ int sc[SEQL];
    const int tid = threadIdx.x;
    const int v = (m[tid] != 0);
    sc[tid] = v;
    __syncthreads();
    for (int o = 1; o < SEQL; o <<= 1) {
        int t = (tid >= o) ? sc[tid - o] : 0;
        __syncthreads();
        sc[tid] += t;
        __syncthreads();
    }
    const int incl = sc[tid];
    const int total = sc[SEQL - 1];
    if (v) { pos[tid] = incl - 1; idx[incl - 1] = tid; }
    else pos[tid] = -1;
    if (tid >= total) idx[tid] = 0;   // disjoint from scatter range
    if (tid == 0) { if (isq) g_scnt[b] = total; else g_kcnt[b - NB] = total; }
}

// ---------------------------------------------------------------------------
// L2 normalize + bf16 hi/lo split, scattered to compacted position
// ---------------------------------------------------------------------------
__device__ __forceinline__ void norm_split(const float* __restrict__ src,
                                           __nv_bfloat16* __restrict__ hid,
                                           __nv_bfloat16* __restrict__ lod) {
    float v[3];
    float s = 0.f;
#pragma unroll
    for (int c = 0; c < 3; c++) {
        v[c] = src[threadIdx.x + c * 256];
        s += v[c] * v[c];
    }
#pragma unroll
    for (int o = 16; o; o >>= 1) s += __shfl_xor_sync(0xffffffffu, s, o);
    __shared__ float ws[8];
    __shared__ float s_inv;
    if ((threadIdx.x & 31) == 0) ws[threadIdx.x >> 5] = s;
    __syncthreads();
    if (threadIdx.x == 0) {
        float t = 0.f;
#pragma unroll
        for (int w = 0; w < 8; w++) t += ws[w];
        s_inv = 1.f / fmaxf(sqrtf(t), 1e-12f);
    }
    __syncthreads();
    float iv = s_inv;
#pragma unroll
    for (int c = 0; c < 3; c++) {
        float x = v[c] * iv;
        __nv_bfloat16 h = __float2bfloat16(x);
        float lo = x - __bfloat162float(h);
        hid[threadIdx.x + c * 256] = h;
        lod[threadIdx.x + c * 256] = __float2bfloat16(lo);
    }
}
__global__ __launch_bounds__(256) void norm_q_kernel(const float* __restrict__ in,
                                                     const int* __restrict__ qm) {
    const int row = blockIdx.x;             // i*512+s
    if (qm[row] == 0) return;               // block-uniform
    const int i = row >> 9;
    const size_t dst = (size_t)i * SEQL + g_spos[row];
    norm_split(in + (size_t)row * HIDD, g_qh + dst * HIDD, g_ql + dst * HIDD);
}
__global__ __launch_bounds__(256) void norm_k_kernel(const float* __restrict__ in,
                                                     const int* __restrict__ km) {
    const int row = blockIdx.x;
    if (km[row] == 0) return;
    const int j = row >> 9;
    const size_t dst = (size_t)j * SEQL + g_tpos[row];
    norm_split(in + (size_t)row * HIDD, g_kh + dst * HIDD, g_kl + dst * HIDD);
}

// ---------------------------------------------------------------------------
// Zero-fill padding rows up to the next 128-tile boundary (parallel over y)
// ---------------------------------------------------------------------------
__global__ __launch_bounds__(256) void pad_zero_kernel() {
    const int b = blockIdx.x;
    const bool isq = (b < NB);
    const int cnt = isq ? g_scnt[b] : g_kcnt[b - NB];
    int pad = (cnt + 127) & ~127;
    if (pad > SEQL) pad = SEQL;
    __nv_bfloat16* h = isq ? (g_qh + (size_t)b * SEQL * HIDD)
                           : (g_kh + (size_t)(b - NB) * SEQL * HIDD);
    __nv_bfloat16* l = isq ? (g_ql + (size_t)b * SEQL * HIDD)
                           : (g_kl + (size_t)(b - NB) * SEQL * HIDD);
    const int n = (pad - cnt) * HIDD;
    const __nv_bfloat16 z = __float2bfloat16(0.f);
    const int start = blockIdx.y * 256 + threadIdx.x;
    const int stride = gridDim.y * 256;
    for (int e = start; e < n; e += stride) {
        h[(size_t)cnt * HIDD + e] = z;
        l[(size_t)cnt * HIDD + e] = z;
    }
}

// ---------------------------------------------------------------------------
// Main: bf16x3 mma.sync GEMM on compacted tiles + fused softmax-score
// ---------------------------------------------------------------------------
__global__ __launch_bounds__(256, 2) void li_mma_kernel(
    const float* __restrict__ alpha_p) {

    extern __shared__ char smem[];
    const uint32_t sb = smem_to_u32(smem);
    const int tid = threadIdx.x;
    const int lane = tid & 31;
    const int w = tid >> 5;
    const int warp_m = w & 3;
    const int warp_n = w >> 2;
    const int stile = blockIdx.x, ttile = blockIdx.y, ij = blockIdx.z;
    const int i = ij >> 4, j = ij & 15;
    const int s0 = stile * BM, t0 = ttile * BN;

    const int scnt = g_scnt[i], kcnt = g_kcnt[j];
    const int qtiles = (scnt + BM - 1) >> 7;
    const int ktiles = (kcnt + BN - 1) >> 7;
    const size_t pidx0 = (((size_t)ij * NST + stile) * NTT + ttile) * BM;

    if (stile >= qtiles || ttile >= ktiles) return;   // finalize never reads these

    float* dtab = (float*)(smem + SM_DTAB);
    float* kmf  = (float*)(smem + SM_KMF);
    int*   tdx  = (int*)(smem + SM_TIDX);
    int*   sdx  = (int*)(smem + SM_SIDX);
    float* rs1s = (float*)(smem + SM_RS1);
    float* rs2s = (float*)(smem + SM_RS2);

    {
        float ar = *alpha_p;
        float alpha = (ar > 0.f) ? ar : 0.01f * ar;
        for (int d = tid; d < SEQL; d += 256) dtab[d] = __expf(-alpha * (float)d);
        if (tid < BN) {
            kmf[tid] = (t0 + tid < kcnt) ? 1.f : 0.f;
            tdx[tid] = g_tidx[j * SEQL + t0 + tid];
        }
        if (tid >= BN && tid < BN + BM) {
            const int r = tid - BN;
            sdx[r] = g_sidx[i * SEQL + s0 + r];
            rs1s[r] = 0.f; rs2s[r] = 0.f;
        }
    }
    __syncthreads();

    const __nv_bfloat16* Ah = g_qh + ((size_t)i * SEQL + s0) * HIDD;
    const __nv_bfloat16* Al = g_ql + ((size_t)i * SEQL + s0) * HIDD;
    const __nv_bfloat16* Bh = g_kh + ((size_t)j * SEQL + t0) * HIDD;
    const __nv_bfloat16* Bl = g_kl + ((size_t)j * SEQL + t0) * HIDD;

    float acc[2][8][4];
#pragma unroll
    for (int mi = 0; mi < 2; mi++)
#pragma unroll
        for (int ni = 0; ni < 8; ni++)
#pragma unroll
            for (int e = 0; e < 4; e++) acc[mi][ni][e] = 0.f;

    auto load_chunk = [&](int ch, int b) {
        const uint32_t base = sb + SM_BUF + b * BUF_BYTES;
        const int k0 = ch * BK;
#pragma unroll
        for (int half = 0; half < 2; half++) {
            const int idx = tid + half * 256;
            const int row = idx >> 2, q = idx & 3;
            const size_t go = (size_t)row * HIDD + k0 + q * 8;
            const uint32_t so = base + row * ROWB + q * 16;
            CP16(so, Ah + go);
            CP16(so + ABYTES, Al + go);
            const uint32_t so2 = base + 2 * ABYTES + row * ROWB + q * 16;
            CP16(so2, Bh + go);
            CP16(so2 + BBYTES, Bl + go);
        }
    };

    auto mma_chunk = [&](int b) {
        const uint32_t abase = sb + SM_BUF + b * BUF_BYTES;
        const uint32_t bbase = abase + 2 * ABYTES;
#pragma unroll
        for (int ks = 0; ks < 2; ks++) {
            const int kb = ks * 32;
            uint32_t ah[2][4], al[2][4];
#pragma unroll
            for (int mi = 0; mi < 2; mi++) {
                const uint32_t r = warp_m * 32 + mi * 16 + (lane & 15);
                const uint32_t ad = abase + r * ROWB + kb + (lane >> 4) * 16;
                LDSM4(ah[mi], ad);
                LDSM4(al[mi], ad + ABYTES);
            }
#pragma unroll
            for (int nh = 0; nh < 2; nh++) {
                uint32_t bhr[2][4], blr[2][4];
#pragma unroll
                for (int bi = 0; bi < 2; bi++) {
                    const int n0 = warp_n * 64 + nh * 32 + bi * 16;
                    const uint32_t rr = n0 + ((lane >> 4) * 8) + (lane & 7);
                    const uint32_t bd = bbase + rr * ROWB + kb + (((lane >> 3) & 1) * 16);
                    LDSM4(bhr[bi], bd);
                    LDSM4(blr[bi], bd + BBYTES);
                }
                // pass-outer issue order: same-accumulator MMAs are 8 apart
                // (per-acc addition order hh->hl->lh preserved => bit-identical)
#pragma unroll
                for (int mi = 0; mi < 2; mi++)
#pragma unroll
                    for (int f = 0; f < 4; f++)
                        mma_bf16(acc[mi][nh * 4 + f], ah[mi],
                                 &bhr[f >> 1][(f & 1) * 2]);          // hi*hi
#pragma unroll
                for (int mi = 0; mi < 2; mi++)
#pragma unroll
                    for (int f = 0; f < 4; f++)
                        mma_bf16(acc[mi][nh * 4 + f], ah[mi],
                                 &blr[f >> 1][(f & 1) * 2]);          // hi*lo
#pragma unroll
                for (int mi = 0; mi < 2; mi++)
#pragma unroll
                    for (int f = 0; f < 4; f++)
                        mma_bf16(acc[mi][nh * 4 + f], al[mi],
                                 &bhr[f >> 1][(f & 1) * 2]);          // lo*hi
            }
        }
    };

    load_chunk(0, 0);
    CP_COMMIT();
    for (int ch = 0; ch < NCH; ch++) {
        if (ch + 1 < NCH) {
            load_chunk(ch + 1, (ch + 1) & 1);
            CP_COMMIT();
            CP_WAIT(1);
        } else {
            CP_WAIT(0);
        }
        __syncthreads();
        mma_chunk(ch & 1);
        __syncthreads();
    }

    // ---- fused epilogue with original-index distance decay ----
    float prs1[2][2], prs2[2][2];
#pragma unroll
    for (int mi = 0; mi < 2; mi++)
#pragma unroll
        for (int h = 0; h < 2; h++) { prs1[mi][h] = 0.f; prs2[mi][h] = 0.f; }

#pragma unroll
    for (int mi = 0; mi < 2; mi++) {
        const int rloc = warp_m * 32 + mi * 16 + (lane >> 2);
        const int sor[2] = { sdx[rloc], sdx[rloc + 8] };
#pragma unroll
        for (int ni = 0; ni < 8; ni++) {
            const int tloc = warp_n * 64 + ni * 8 + (lane & 3) * 2;
#pragma unroll
            for (int e = 0; e < 4; e++) {
                const int sorr = sor[e >> 1];
                const int torr = tdx[tloc + (e & 1)];
                const float cv = acc[mi][ni][e];
                int d = sorr - torr; if (d < 0) d = -d;
                const float ee = kmf[tloc + (e & 1)] * __expf(cv * dtab[d]);
                prs1[mi][e >> 1] += ee;
                prs2[mi][e >> 1] += ee * cv;
            }
        }
    }

#pragma unroll
    for (int mi = 0; mi < 2; mi++)
#pragma unroll
        for (int h = 0; h < 2; h++) {
            float v1 = prs1[mi][h], v2 = prs2[mi][h];
            v1 += __shfl_xor_sync(0xffffffffu, v1, 1);
            v1 += __shfl_xor_sync(0xffffffffu, v1, 2);
            v2 += __shfl_xor_sync(0xffffffffu, v2, 1);
            v2 += __shfl_xor_sync(0xffffffffu, v2, 2);
            if ((lane & 3) == 0) {
                const int lr = warp_m * 32 + mi * 16 + (lane >> 2) + h * 8;
                atomicAdd(&rs1s[lr], v1);   // exactly 2 addends/row -> deterministic
                atomicAdd(&rs2s[lr], v2);
            }
        }
    __syncthreads();

    if (tid < BM) {
        g_pS1[pidx0 + tid] = rs1s[tid];
        g_pS2[pidx0 + tid] = rs2s[tid];
    }
}

// ---------------------------------------------------------------------------
// Finalize: count-aware sum over ACTIVE tiles only (pads self-cancel)
// ---------------------------------------------------------------------------
__global__ __launch_bounds__(256) void finalize_kernel(float* __restrict__ out) {
    const int z = blockIdx.x;           // ij = i*16+j
    const int i = z >> 4, j = z & 15;
    const int qtiles = (g_scnt[i] + BM - 1) >> 7;
    const int ktiles = (g_kcnt[j] + BN - 1) >> 7;
    __shared__ float red[256];
    float acc = 0.f;
    for (int s = threadIdx.x; s < qtiles * BM; s += 256) {
        const int stile = s >> 7, r = s & 127;
        const size_t base = (((size_t)z * NST + stile) * NTT) * BM + r;
        float S1 = 0.f, S2 = 0.f;
        for (int tt = 0; tt < ktiles; tt++) {   // fixed order: deterministic
            S1 += g_pS1[base + (size_t)tt * BM];
            S2 += g_pS2[base + (size_t)tt * BM];
        }
        acc += (S1 > 0.f) ? (S2 / S1) : 0.f;
    }
    red[threadIdx.x] = acc;
    __syncthreads();
    for (int o = 128; o; o >>= 1) {
        if (threadIdx.x < (unsigned)o) red[threadIdx.x] += red[threadIdx.x + o];
        __syncthreads();
    }
    if (threadIdx.x == 0) out[z] = red[0];
}

// ---------------------------------------------------------------------------
extern "C" void kernel_launch(void* const* d_in, const int* in_sizes, int n_in,
                              void* d_out, int out_size) {
    const float* q     = (const float*)d_in[0];
    const float* k     = (const float*)d_in[1];
    const float* alpha = (const float*)d_in[2];
    const int*   qm    = (const int*)d_in[3];
    const int*   kmm   = (const int*)d_in[4];
    float* out = (float*)d_out;

    cudaFuncSetAttribute(li_mma_kernel, cudaFuncAttributeMaxDynamicSharedMemorySize,
                         SMEM_TOTAL);

    scan_kernel<<<NB + NKB, 512>>>(qm, kmm);
    norm_q_kernel<<<NB * SEQL, 256>>>(q, qm);
    norm_k_kernel<<<NKB * SEQL, 256>>>(k, kmm);
    {
        dim3 pg(NB + NKB, 16);
        pad_zero_kernel<<<pg, 256>>>();
    }

    dim3 grid(NST, NTT, NB * NKB);
    li_mma_kernel<<<grid, 256, SMEM_TOTAL>>>(alpha);

    finalize_kernel<<<NB * NKB, 256>>>(out);
}